// round 4
// baseline (speedup 1.0000x reference)
#include <cuda_runtime.h>
#include <cuda_bf16.h>
#include <cstdint>

#define NTAGS 128
#define BATCH 256
#define SLEN  512
#define NTHR  256            // 2 threads per tag: (j, h)
#define PBSTRIDE 136         // floats per p-buffer: 64 + 4 pad + 64 + 4 pad

// ---- packed f32x2 helpers (sm_103a) ----
__device__ __forceinline__ unsigned long long pk2(float x, float y) {
    unsigned long long r;
    asm("mov.b64 %0,{%1,%2};" : "=l"(r) : "f"(x), "f"(y));
    return r;
}
__device__ __forceinline__ void upk2(unsigned long long v, float& x, float& y) {
    asm("mov.b64 {%0,%1},%2;" : "=f"(x), "=f"(y) : "l"(v));
}
__device__ __forceinline__ unsigned long long ffma2(unsigned long long a,
                                                    unsigned long long b,
                                                    unsigned long long c) {
    unsigned long long d;
    asm("fma.rn.f32x2 %0,%1,%2,%3;" : "=l"(d) : "l"(a), "l"(b), "l"(c));
    return d;
}

__global__ void crf_zero_out(float* out) { out[0] = 0.0f; }

__global__ void __launch_bounds__(NTHR)
crf_forward_kernel(const float* __restrict__ emissions,      // [B,S,NTAGS]
                   const void* __restrict__ tags_raw,        // [B,S] int32 OR int64
                   const unsigned char* __restrict__ mask,   // [B,S]
                   const float* __restrict__ transitions,    // [NTAGS,NTAGS]
                   float* __restrict__ out)                  // [1]
{
    const int b    = blockIdx.x;
    const int tid  = threadIdx.x;
    const int lane = tid & 31;
    const int wid  = tid >> 5;
    const int j    = tid >> 1;            // tag index (0..127), shared by a lane pair
    const int h    = tid & 1;             // which half of the i-range this thread sums

    // p buffers: [0,64) at float offset 0, [64,128) at float offset 68 (16B pad
    // => the two broadcast addresses per LDS.128 hit disjoint bank groups)
    __shared__ __align__(16) float pbuf[2 * PBSTRIDE];
    __shared__ float r0s[2];
    __shared__ float red[8];

    // -------- tags dtype auto-detect (int64 vs int32) --------
    const int* tg32_all = (const int*)tags_raw;
    int det = 0;
#pragma unroll
    for (int i = 0; i < 64; i++) det |= tg32_all[2 * i + 1];
    const int tstride = (det == 0) ? 2 : 1;

    // ---------------- prologue: eT half-column into registers ----------------
    // col[k] = (exp T[64h+2k][j], exp T[64h+2k+1][j])
    unsigned long long col[32];
#pragma unroll
    for (int k = 0; k < 32; k++) {
        int i0 = h * 64 + 2 * k;
        float t0 = transitions[(size_t)i0       * NTAGS + j];
        float t1 = transitions[(size_t)(i0 + 1) * NTAGS + j];
        col[k] = pk2(expf(t0), expf(t1));
    }

    // ---------------- gold score (gather-sum over all 256 threads) ----------------
    const int*           tg = tg32_all + (size_t)b * SLEN * tstride;
    const unsigned char* mk = mask + (size_t)b * SLEN;
    const float*         em = emissions + (size_t)b * SLEN * NTAGS;

    float gold = 0.0f;
#pragma unroll
    for (int t = tid; t < SLEN; t += NTHR) {
        int   tt = tg[t * tstride];
        float m  = mk[t] ? 1.0f : 0.0f;
        gold += m * em[(size_t)t * NTAGS + tt];
        if (t + 1 < SLEN) {
            int   t2 = tg[(t + 1) * tstride];
            float m2 = mk[t + 1] ? 1.0f : 0.0f;
            gold += m2 * transitions[(size_t)tt * NTAGS + t2];
        }
    }

    // ---------------- forward scan ----------------
    // invariant: alpha_j = C + r_j ; cref = r0 from previous step (stale-but-exact)
    float r = em[j];                       // alpha0
    if (tid == 0) r0s[0] = r;
    double C = 0.0;

    // emission prefetch ring, depth 4 (MLP=4 hides DRAM latency)
    float ering[4];
#pragma unroll
    for (int i = 0; i < 4; i++)
        ering[i] = em[(size_t)(1 + i) * NTAGS + j];

    __syncthreads();
    float cref = r0s[0];

    // my half of p, as ulonglong2 chunks (base depends on h; buf adds PBSTRIDE floats)
    const char* pbase = (const char*)pbuf + h * 272;
    const int   my_slot = (j < 64) ? j : (68 + (j - 64));   // where p[j] lives

    for (int t = 1; t < SLEN; t++) {
        const int buf = t & 1;
        float p = __expf(r - cref);
        if (h == 0) pbuf[buf * PBSTRIDE + my_slot] = p;
        if (tid == 0) r0s[buf] = r;
        float e_cur = ering[(t - 1) & 3];
        if (t + 4 < SLEN)
            ering[(t - 1) & 3] = em[(size_t)(t + 4) * NTAGS + j];
        __syncthreads();                   // single barrier per step
        float cnew = r0s[buf];

        // partial matvec over 64 i's: 16 LDS.128, 32 FFMA2, 4 accumulators
        const ulonglong2* pq = (const ulonglong2*)(pbase + buf * (PBSTRIDE * 4));
        unsigned long long a0 = 0ull, a1 = 0ull, a2 = 0ull, a3 = 0ull;
#pragma unroll
        for (int k = 0; k < 16; k += 2) {
            ulonglong2 q0 = pq[k];
            ulonglong2 q1 = pq[k + 1];
            a0 = ffma2(q0.x, col[2 * k],     a0);
            a1 = ffma2(q0.y, col[2 * k + 1], a1);
            a2 = ffma2(q1.x, col[2 * k + 2], a2);
            a3 = ffma2(q1.y, col[2 * k + 3], a3);
        }
        float x0, y0, x1, y1, x2, y2, x3, y3;
        upk2(a0, x0, y0); upk2(a1, x1, y1);
        upk2(a2, x2, y2); upk2(a3, x3, y3);
        float sh = ((x0 + x1) + (x2 + x3)) + ((y0 + y1) + (y2 + y3));
        float s  = sh + __shfl_xor_sync(0xFFFFFFFFu, sh, 1);   // pair-reduce

        C += (double)cref;
        r  = __logf(s) + e_cur;
        cref = cnew;
    }

    // ---------------- partition = C + logsumexp_j(r) ----------------
    // every j appears twice (h=0,1 hold bitwise-identical r) => sumexp is 2x
    float m = r;
#pragma unroll
    for (int o = 16; o > 0; o >>= 1)
        m = fmaxf(m, __shfl_xor_sync(0xFFFFFFFFu, m, o));
    if (lane == 0) red[wid] = m;
    __syncthreads();
    m = fmaxf(fmaxf(fmaxf(red[0], red[1]), fmaxf(red[2], red[3])),
              fmaxf(fmaxf(red[4], red[5]), fmaxf(red[6], red[7])));
    __syncthreads();

    float ex = __expf(r - m);
#pragma unroll
    for (int o = 16; o > 0; o >>= 1)
        ex += __shfl_xor_sync(0xFFFFFFFFu, ex, o);
    if (lane == 0) red[wid] = ex;
    __syncthreads();
    float sumex = ((red[0] + red[1]) + (red[2] + red[3])) +
                  ((red[4] + red[5]) + (red[6] + red[7]));
    __syncthreads();

#pragma unroll
    for (int o = 16; o > 0; o >>= 1)
        gold += __shfl_xor_sync(0xFFFFFFFFu, gold, o);
    if (lane == 0) red[wid] = gold;
    __syncthreads();
    float goldtot = ((red[0] + red[1]) + (red[2] + red[3])) +
                    ((red[4] + red[5]) + (red[6] + red[7]));

    if (tid == 0) {
        float part = (float)(C + (double)(m + __logf(sumex * 0.5f)));
        atomicAdd(out, part - goldtot);
    }
}

extern "C" void kernel_launch(void* const* d_in, const int* in_sizes, int n_in,
                              void* d_out, int out_size) {
    const float*         emissions   = (const float*)d_in[0];
    const void*          tags        = (const void*)d_in[1];
    const unsigned char* mask        = (const unsigned char*)d_in[2];
    const float*         transitions = (const float*)d_in[3];
    float*               out         = (float*)d_out;

    crf_zero_out<<<1, 1>>>(out);
    crf_forward_kernel<<<BATCH, NTHR>>>(emissions, tags, mask, transitions, out);
}

// round 8
// speedup vs baseline: 1.2005x; 1.2005x over previous
#include <cuda_runtime.h>
#include <cuda_bf16.h>
#include <cstdint>

#define NTAGS 128
#define BATCH 256
#define SLEN  512

// ---- packed f32x2 helpers (sm_103a) ----
__device__ __forceinline__ unsigned long long pk2(float x, float y) {
    unsigned long long r;
    asm("mov.b64 %0,{%1,%2};" : "=l"(r) : "f"(x), "f"(y));
    return r;
}
__device__ __forceinline__ void upk2(unsigned long long v, float& x, float& y) {
    asm("mov.b64 {%0,%1},%2;" : "=f"(x), "=f"(y) : "l"(v));
}
__device__ __forceinline__ unsigned long long ffma2(unsigned long long a,
                                                    unsigned long long b,
                                                    unsigned long long c) {
    unsigned long long d;
    asm("fma.rn.f32x2 %0,%1,%2,%3;" : "=l"(d) : "l"(a), "l"(b), "l"(c));
    return d;
}
__device__ __forceinline__ unsigned long long add2(unsigned long long a,
                                                   unsigned long long b) {
    unsigned long long d;
    asm("add.rn.f32x2 %0,%1,%2;" : "=l"(d) : "l"(a), "l"(b));
    return d;
}

__global__ void crf_zero_out(float* out) { out[0] = 0.0f; }

__global__ void __launch_bounds__(NTAGS, 2)
crf_forward_kernel(const float* __restrict__ emissions,      // [B,S,NTAGS]
                   const void* __restrict__ tags_raw,        // [B,S] int32 OR int64
                   const unsigned char* __restrict__ mask,   // [B,S]
                   const float* __restrict__ transitions,    // [NTAGS,NTAGS]
                   float* __restrict__ out)                  // [1]
{
    const int b    = blockIdx.x;
    const int j    = threadIdx.x;         // tag owned by this thread
    const int lane = j & 31;
    const int wid  = j >> 5;

    __shared__ __align__(16) float pbuf[2][NTAGS];  // double-buffered w
    __shared__ float u0s[2];                        // double-buffered u0 broadcast
    __shared__ float red[4];

    // -------- tags dtype auto-detect (int64 vs int32) --------
    const int* tg32_all = (const int*)tags_raw;
    int det = 0;
#pragma unroll
    for (int i = 0; i < 64; i++) det |= tg32_all[2 * i + 1];
    const int tstride = (det == 0) ? 2 : 1;

    // ---------------- prologue: eT column j into registers ----------------
    unsigned long long col[NTAGS / 2];
#pragma unroll
    for (int k = 0; k < NTAGS / 2; k++) {
        float t0 = transitions[(size_t)(2 * k)     * NTAGS + j];
        float t1 = transitions[(size_t)(2 * k + 1) * NTAGS + j];
        col[k] = pk2(expf(t0), expf(t1));
    }

    // ---------------- gold score ----------------
    const int*           tg = tg32_all + (size_t)b * SLEN * tstride;
    const unsigned char* mk = mask + (size_t)b * SLEN;
    const float*         em = emissions + (size_t)b * SLEN * NTAGS;

    float gold = 0.0f;
#pragma unroll
    for (int t = j; t < SLEN; t += NTAGS) {
        int   tt = tg[t * tstride];
        float m  = mk[t] ? 1.0f : 0.0f;
        gold += m * em[(size_t)t * NTAGS + tt];
        if (t + 1 < SLEN) {
            int   t2 = tg[(t + 1) * tstride];
            float m2 = mk[t + 1] ? 1.0f : 0.0f;
            gold += m2 * transitions[(size_t)tt * NTAGS + t2];
        }
    }

    // ---------------- product-domain forward scan ----------------
    // invariant: exp(alpha_j(t)) = e^{C-ish} * exp(e_j(t)) * u_j(t)
    // w_j(t) = u_j(t) * exp(e_j(t)) / u0(t-1)  (1-step-stale normalizer, exact:
    //   the same u0 divided out of w is the one whose log is added to C)
    float e0 = em[j];
    if (j == 0) u0s[0] = e0;              // broadcast c0 = e_0(0)
    // emission prefetch ring, depth 4
    float ering[4];
#pragma unroll
    for (int i = 0; i < 4; i++)
        ering[i] = em[(size_t)(1 + i) * NTAGS + j];
    __syncthreads();
    float c0 = u0s[0];
    double C = (double)c0;

    float w      = __expf(e0 - c0);       // w(0)
    float u_prev = 1.0f;                  // u0 placeholder for first publish
    float u      = 1.0f;
    float E_cur  = 1.0f;

    for (int t = 1; t < SLEN; t++) {
        const int buf = t & 1;
        pbuf[buf][j] = w;
        if (j == 0) u0s[buf] = u_prev;    // publish raw u_0(t-1)
        float e_cur = ering[(t - 1) & 3];
        if (t + 4 < SLEN)
            ering[(t - 1) & 3] = em[(size_t)(t + 4) * NTAGS + j];
        E_cur = __expf(e_cur);            // exp(e_j(t)) — off critical chain
        __syncthreads();                  // single barrier per step
        float u0r = u0s[buf];
        float rcp;                        // MUFU rcp, off critical chain
        asm("rcp.approx.f32 %0,%1;" : "=f"(rcp) : "f"(u0r));

        // matvec: u_j = sum_i w_i * eT[i][j]   (8 accumulators, chain depth 8)
        const ulonglong2* pq = (const ulonglong2*)pbuf[buf];
        unsigned long long a0 = 0ull, a1 = 0ull, a2 = 0ull, a3 = 0ull;
        unsigned long long a4 = 0ull, a5 = 0ull, a6 = 0ull, a7 = 0ull;
#pragma unroll
        for (int k = 0; k < 32; k += 4) {
            ulonglong2 q0 = pq[k];
            ulonglong2 q1 = pq[k + 1];
            ulonglong2 q2 = pq[k + 2];
            ulonglong2 q3 = pq[k + 3];
            a0 = ffma2(q0.x, col[2 * k],     a0);
            a1 = ffma2(q0.y, col[2 * k + 1], a1);
            a2 = ffma2(q1.x, col[2 * k + 2], a2);
            a3 = ffma2(q1.y, col[2 * k + 3], a3);
            a4 = ffma2(q2.x, col[2 * k + 4], a4);
            a5 = ffma2(q2.y, col[2 * k + 5], a5);
            a6 = ffma2(q3.x, col[2 * k + 6], a6);
            a7 = ffma2(q3.y, col[2 * k + 7], a7);
        }
        unsigned long long s01 = add2(add2(a0, a1), add2(a2, a3));
        unsigned long long s23 = add2(add2(a4, a5), add2(a6, a7));
        unsigned long long st  = add2(s01, s23);
        float sx, sy;
        upk2(st, sx, sy);
        u = sx + sy;

        if (t < SLEN - 1) {
            C += (double)__logf(u0r);     // account the scale actually applied
            w  = u * (E_cur * rcp);       // w(t): ONE fmul on the chain
        }
        u_prev = u;
    }

    // ---------------- partition = C + log(sum_j u_j(T) * exp(e_j(T))) --------
    float z = u * E_cur;                  // all positive, within fp32 range
#pragma unroll
    for (int o = 16; o > 0; o >>= 1)
        z += __shfl_xor_sync(0xFFFFFFFFu, z, o);
    if (lane == 0) red[wid] = z;
    __syncthreads();
    float sumz = (red[0] + red[1]) + (red[2] + red[3]);
    __syncthreads();

    // reduce gold across block
#pragma unroll
    for (int o = 16; o > 0; o >>= 1)
        gold += __shfl_xor_sync(0xFFFFFFFFu, gold, o);
    if (lane == 0) red[wid] = gold;
    __syncthreads();
    float goldtot = (red[0] + red[1]) + (red[2] + red[3]);

    if (j == 0) {
        float part = (float)(C + (double)__logf(sumz));
        atomicAdd(out, part - goldtot);
    }
}

extern "C" void kernel_launch(void* const* d_in, const int* in_sizes, int n_in,
                              void* d_out, int out_size) {
    const float*         emissions   = (const float*)d_in[0];
    const void*          tags        = (const void*)d_in[1];
    const unsigned char* mask        = (const unsigned char*)d_in[2];
    const float*         transitions = (const float*)d_in[3];
    float*               out         = (float*)d_out;

    crf_zero_out<<<1, 1>>>(out);
    crf_forward_kernel<<<BATCH, NTAGS>>>(emissions, tags, mask, transitions, out);
}